// round 5
// baseline (speedup 1.0000x reference)
#include <cuda_runtime.h>

// Problem constants
#define BB    256
#define TTOT  16384
#define ALPHA_F 0.95f

// LIF chunking
#define LCHUNK 128
#define WARM   512
#define NCHUNK (TTOT / LCHUNK)   // 128
#define NWORD  (TTOT / 32)       // 512 mask words per (b,ch)

// Scratch (device globals: allocation-free)
__device__ float    g_uT[3 * TTOT * BB];          // u transposed: [ch][t][b]
__device__ unsigned g_smask[BB * 3 * NWORD];      // spike bitmasks [b][ch][w]

// ---------------------------------------------------------------------------
// Kernel 1: causal conv. Block = 256 thr = tile of 32 b x 64 t.
// Writes u (output layout, via smem transpose) AND g_uT (direct, coalesced).
// thread: b_r = tid&31 (lane = batch), tgrp = tid>>5 -> 8 consecutive t.
// ---------------------------------------------------------------------------
__global__ __launch_bounds__(256) void conv_kernel(
    const float* __restrict__ x,
    const float* __restrict__ w0,
    const float* __restrict__ w1,
    const float* __restrict__ w2,
    float* __restrict__ u)
{
    __shared__ float xs[32 * 97];    // [32 b][95 cols + pad->97]; stride 97 (odd)
    __shared__ float us[32 * 193];   // [32 b][3 ch * 64 t], stride 193 (odd)

    const int tid   = threadIdx.x;
    const int bbase = blockIdx.x * 32;    // 0..224
    const int t0    = blockIdx.y * 64;    // 0..16320

    // stage x tile: rows b, cols = t0-31 .. t0+63 (95 cols)
    for (int idx = tid; idx < 32 * 95; idx += 256) {
        int r = idx / 95;
        int i = idx - r * 95;
        int gt = t0 - 31 + i;
        xs[r * 97 + i] = (gt >= 0) ? x[(size_t)(bbase + r) * TTOT + gt] : 0.0f;
    }
    __syncthreads();

    const int b_r  = tid & 31;
    const int tgrp = tid >> 5;
    const float* xrow = &xs[b_r * 97 + tgrp * 8];   // xv[j] = xrow[j], j=0..38

    float xv[39];
#pragma unroll
    for (int j = 0; j < 39; j++) xv[j] = xrow[j];

    float a0[8], a1[8], a2[8];
#pragma unroll
    for (int i = 0; i < 8; i++) { a0[i] = 0.f; a1[i] = 0.f; a2[i] = 0.f; }

    {   // k=32 branch (cols tl .. tl+31)
        float W[32];
#pragma unroll
        for (int i = 0; i < 32; i++) W[i] = w2[i] * 0.1767766952966369f;
#pragma unroll
        for (int kk = 0; kk < 32; kk++)
#pragma unroll
            for (int i = 0; i < 8; i++)
                a2[i] = fmaf(W[kk], xv[i + kk], a2[i]);
    }
    {   // k=16 branch (cols tl+16 .. tl+31)
        float W[16];
#pragma unroll
        for (int i = 0; i < 16; i++) W[i] = w1[i] * 0.25f;
#pragma unroll
        for (int kk = 0; kk < 16; kk++)
#pragma unroll
            for (int i = 0; i < 8; i++)
                a1[i] = fmaf(W[kk], xv[i + 16 + kk], a1[i]);
    }
    {   // k=8 branch (cols tl+24 .. tl+31)
        float W[8];
#pragma unroll
        for (int i = 0; i < 8; i++) W[i] = w0[i] * 0.3535533905932738f;
#pragma unroll
        for (int kk = 0; kk < 8; kk++)
#pragma unroll
            for (int i = 0; i < 8; i++)
                a0[i] = fmaf(W[kk], xv[i + 24 + kk], a0[i]);
    }

    // u_T write: lanes vary b -> 128B coalesced per (ch, t)
    {
        const int tl0 = t0 + tgrp * 8;
#pragma unroll
        for (int i = 0; i < 8; i++) {
            g_uT[(size_t)(0 * TTOT + tl0 + i) * BB + bbase + b_r] = a0[i];
            g_uT[(size_t)(1 * TTOT + tl0 + i) * BB + bbase + b_r] = a1[i];
            g_uT[(size_t)(2 * TTOT + tl0 + i) * BB + bbase + b_r] = a2[i];
        }
    }

    // normal-layout u via smem transpose
    {
        const int c0 = tgrp * 8;
        float* ur = &us[b_r * 193];
#pragma unroll
        for (int i = 0; i < 8; i++) {
            ur[0 * 64 + c0 + i] = a0[i];
            ur[1 * 64 + c0 + i] = a1[i];
            ur[2 * 64 + c0 + i] = a2[i];
        }
    }
    __syncthreads();

    // drain: 96 rows (b,ch) x 16 float4 = 1536 float4, 6 per thread
#pragma unroll
    for (int j = 0; j < 6; j++) {
        int idx = j * 256 + tid;
        int row = idx >> 4;          // 0..95
        int o   = idx & 15;
        int br  = row / 3;
        int ch  = row - br * 3;
        const float* p = &us[br * 193 + ch * 64 + 4 * o];
        float4 v = make_float4(p[0], p[1], p[2], p[3]);
        float* g = u + ((size_t)((bbase + br) * 3 + ch)) * TTOT + t0 + 4 * o;
        *reinterpret_cast<float4*>(g) = v;
    }
}

// ---------------------------------------------------------------------------
// Kernel 2: LIF + WTA scan, barrier-free. Block = 256 thr = one chunk x 256 b.
// Reads g_uT (every LDG = one 128B line), writes spike bitmasks to g_smask.
// 8-step register double buffer hides L1/L2 latency.
// ---------------------------------------------------------------------------
#define LIF_STEP(uu0, uu1, uu2, SPIKE)                                         \
    {                                                                          \
        const float w0v = fmaf(ALPHA_F, y0, (uu0));                            \
        const float w1v = fmaf(ALPHA_F, y1, (uu1));                            \
        const float w2v = fmaf(ALPHA_F, y2, (uu2));                            \
        const bool g01 = (w0v >= w1v), g02 = (w0v >= w2v), g12 = (w1v >= w2v); \
        const bool f0 = g01 & g02 & (w0v >= 1.0f);                             \
        const bool f1 = (!g01) & g12 & (w1v >= 1.0f);                          \
        const bool f2 = (!g02) & (!g12) & (w2v >= 1.0f);                       \
        y0 = w0v - (f0 ? 1.0f : 0.0f);                                         \
        y1 = w1v - (f1 ? 1.0f : 0.0f);                                         \
        y2 = w2v - (f2 ? 1.0f : 0.0f);                                         \
        SPIKE                                                                  \
    }

__global__ __launch_bounds__(256) void lif_kernel()
{
    const int b = threadIdx.x;            // batch 0..255
    const int c = blockIdx.x;             // chunk 0..127

    const int commit = c * LCHUNK;
    int start = commit - WARM; if (start < 0) start = 0;

    const float* p0 = g_uT + (size_t)0 * TTOT * BB + b;
    const float* p1 = g_uT + (size_t)1 * TTOT * BB + b;
    const float* p2 = g_uT + (size_t)2 * TTOT * BB + b;

    float y0 = 0.f, y1 = 0.f, y2 = 0.f;

    // rolling 8-step buffers
    float c0[8], c1[8], c2[8], n0[8], n1[8], n2[8];

#define LOAD8(dst0, dst1, dst2, tt)                                            \
    {                                                                          \
        _Pragma("unroll")                                                      \
        for (int r = 0; r < 8; r++) {                                          \
            dst0[r] = p0[(size_t)((tt) + r) * BB];                             \
            dst1[r] = p1[(size_t)((tt) + r) * BB];                             \
            dst2[r] = p2[(size_t)((tt) + r) * BB];                             \
        }                                                                      \
    }

    LOAD8(c0, c1, c2, start);

    // ---- warm-up: [start, commit), multiple of 8, no spikes recorded ----
    for (int t = start; t < commit; t += 8) {
#pragma unroll
        for (int r = 0; r < 8; r++) { n0[r] = c0[r]; n1[r] = c1[r]; n2[r] = c2[r]; }
        LOAD8(c0, c1, c2, t + 8);          // next group (commit prefetch incl.)
#pragma unroll
        for (int r = 0; r < 8; r++)
            LIF_STEP(n0[r], n1[r], n2[r], )
    }

    // ---- commit: 4 groups of 32 steps, bitmask per channel ----
    unsigned* mrow = g_smask + (size_t)(b * 3) * NWORD + c * (LCHUNK / 32);
#pragma unroll
    for (int gblk = 0; gblk < LCHUNK / 32; gblk++) {
        unsigned m0 = 0u, m1 = 0u, m2 = 0u;
#pragma unroll
        for (int sb = 0; sb < 4; sb++) {
            const int t = commit + gblk * 32 + sb * 8;
#pragma unroll
            for (int r = 0; r < 8; r++) { n0[r] = c0[r]; n1[r] = c1[r]; n2[r] = c2[r]; }
            if (t + 8 < commit + LCHUNK) LOAD8(c0, c1, c2, t + 8);
#pragma unroll
            for (int r = 0; r < 8; r++) {
                const unsigned bit = 1u << (sb * 8 + r);
                LIF_STEP(n0[r], n1[r], n2[r],
                         if (f0) m0 |= bit; if (f1) m1 |= bit; if (f2) m2 |= bit;)
            }
        }
        mrow[0 * NWORD + gblk] = m0;
        mrow[1 * NWORD + gblk] = m1;
        mrow[2 * NWORD + gblk] = m2;
    }
#undef LOAD8
}

// ---------------------------------------------------------------------------
// Kernel 3: expand bitmasks -> s floats. idx enumerates (b,ch,w) in the same
// order as s rows, so s + idx*32 is the right 32-float span. Fully coalesced.
// ---------------------------------------------------------------------------
__global__ __launch_bounds__(256) void expand_kernel(float* __restrict__ s)
{
    const int idx = blockIdx.x * 256 + threadIdx.x;   // 0 .. 256*3*512-1
    const unsigned m = g_smask[idx];
    float* out = s + (size_t)idx * 32;
#pragma unroll
    for (int q = 0; q < 8; q++) {
        float4 v;
        v.x = (m >> (4 * q + 0)) & 1u ? 1.0f : 0.0f;
        v.y = (m >> (4 * q + 1)) & 1u ? 1.0f : 0.0f;
        v.z = (m >> (4 * q + 2)) & 1u ? 1.0f : 0.0f;
        v.w = (m >> (4 * q + 3)) & 1u ? 1.0f : 0.0f;
        *reinterpret_cast<float4*>(out + 4 * q) = v;
    }
}

// ---------------------------------------------------------------------------
// Launch. Inputs: x [256*16384], w0 [8], w1 [16], w2 [32], y (unused).
// Output: concat(u, s_all), both [256, 3, 16384] float32.
// ---------------------------------------------------------------------------
extern "C" void kernel_launch(void* const* d_in, const int* in_sizes, int n_in,
                              void* d_out, int out_size)
{
    const float* x  = (const float*)d_in[0];
    const float* w0 = (const float*)d_in[1];
    const float* w1 = (const float*)d_in[2];
    const float* w2 = (const float*)d_in[3];

    float* u = (float*)d_out;
    float* s = u + (size_t)BB * 3 * TTOT;

    dim3 cgrid(BB / 32, TTOT / 64);
    conv_kernel<<<cgrid, 256>>>(x, w0, w1, w2, u);

    lif_kernel<<<NCHUNK, 256>>>();

    expand_kernel<<<(BB * 3 * NWORD) / 256, 256>>>(s);
}

// round 6
// speedup vs baseline: 1.3073x; 1.3073x over previous
#include <cuda_runtime.h>

// Problem constants
#define BB   256
#define TTOT 16384
#define ALPHA_F 0.95f

// LIF chunking (R3-verified exact): 64 chunks of 256, warm-up 512
#define LCHUNK 256
#define WARM   512
#define NCHUNK (TTOT / LCHUNK)   // 64

// lif smem tiling: tile = [3ch][32 t][128 b pad 129]
#define TTILE 32
#define BPAD  129
#define CHSZ  (TTILE * BPAD)            // 4128 floats
#define UBUF  (3 * CHSZ)                // 12384 floats = 49536 B
#define LIF_SMEM_BYTES (4 * UBUF * 4)   // 2 u-buffers + 2 s-buffers = 198144 B

// ---------------------------------------------------------------------------
// Kernel 1: causal conv (R3 version, measured ~21.6us).
// ---------------------------------------------------------------------------
__global__ __launch_bounds__(512) void conv_kernel(
    const float* __restrict__ x,
    const float* __restrict__ w0,
    const float* __restrict__ w1,
    const float* __restrict__ w2,
    float* __restrict__ u)
{
    __shared__ float xs[2080];      // 31 halo + 2048 tile (+1 pad)

    const int b    = blockIdx.x;    // 0..255
    const int tile = blockIdx.y;    // 0..7
    const int t0   = tile * 2048;
    const float* xb = x + (size_t)b * TTOT;

    for (int i = threadIdx.x; i < 2080; i += 512) {
        int gi = t0 + i - 31;
        xs[i] = (gi >= 0 && gi < TTOT) ? xb[gi] : 0.0f;
    }

    float W2[32], W1[16], W0[8];
#pragma unroll
    for (int i = 0; i < 32; i++) W2[i] = w2[i] * 0.1767766952966369f;   // 1/sqrt(32)
#pragma unroll
    for (int i = 0; i < 16; i++) W1[i] = w1[i] * 0.25f;                 // 1/sqrt(16)
#pragma unroll
    for (int i = 0; i < 8;  i++) W0[i] = w0[i] * 0.3535533905932738f;   // 1/sqrt(8)

    __syncthreads();

    const int tt0 = threadIdx.x * 4;

    float xv[36];
#pragma unroll
    for (int q = 0; q < 9; q++) {
        float4 v = *reinterpret_cast<const float4*>(&xs[tt0 + 4 * q]);
        xv[4 * q + 0] = v.x; xv[4 * q + 1] = v.y;
        xv[4 * q + 2] = v.z; xv[4 * q + 3] = v.w;
    }

    float a0[4] = {0.f, 0.f, 0.f, 0.f};
    float a1[4] = {0.f, 0.f, 0.f, 0.f};
    float a2[4] = {0.f, 0.f, 0.f, 0.f};

#pragma unroll
    for (int kk = 0; kk < 32; kk++)
#pragma unroll
        for (int r = 0; r < 4; r++)
            a2[r] = fmaf(W2[kk], xv[kk + r], a2[r]);
#pragma unroll
    for (int kk = 0; kk < 16; kk++)
#pragma unroll
        for (int r = 0; r < 4; r++)
            a1[r] = fmaf(W1[kk], xv[16 + kk + r], a1[r]);
#pragma unroll
    for (int kk = 0; kk < 8; kk++)
#pragma unroll
        for (int r = 0; r < 4; r++)
            a0[r] = fmaf(W0[kk], xv[24 + kk + r], a0[r]);

    const int t = t0 + tt0;
    float* ub = u + (size_t)b * 3 * TTOT;
    *reinterpret_cast<float4*>(ub + 0 * TTOT + t) = make_float4(a0[0], a0[1], a0[2], a0[3]);
    *reinterpret_cast<float4*>(ub + 1 * TTOT + t) = make_float4(a1[0], a1[1], a1[2], a1[3]);
    *reinterpret_cast<float4*>(ub + 2 * TTOT + t) = make_float4(a2[0], a2[1], a2[2], a2[3]);
}

// ---------------------------------------------------------------------------
// Kernel 2: LIF + WTA scan, warp-specialized.
// Block = 256 thr: warps 0-3 consumers (scan, 1 batch each of 128),
// warps 4-7 producers (stage next u tile, drain spike tiles).
// Grid = 128 = (chunk 0..63) x (batch half). One __syncthreads per tile.
// ---------------------------------------------------------------------------
__global__ __launch_bounds__(256) void lif_kernel(
    const float* __restrict__ u,
    float* __restrict__ s)
{
    extern __shared__ float sm[];
    float* ubuf[2] = { sm, sm + UBUF };
    float* sbuf[2] = { sm + 2 * UBUF, sm + 3 * UBUF };

    const int tid   = threadIdx.x;
    const int c     = (int)blockIdx.x >> 1;
    const int bbase = ((int)blockIdx.x & 1) << 7;

    const int commit = c * LCHUNK;
    int start = commit - WARM; if (start < 0) start = 0;
    const int ntiles    = (commit + LCHUNK - start) >> 5;
    const int commit_i0 = (commit - start) >> 5;   // first commit tile index

    const bool is_prod = (tid >= 128);
    const int  ptid    = tid & 127;                // role-local id

    // producer staging map: 3072 16B-chunks per tile, 24 per producer thread.
    // idx = (h*12 + j)*128 + ptid ; o = idx&7 ; row = idx>>3 (= ch*128 + br)
#define LD_BATCH(t0v, h, pf)                                                   \
    {                                                                          \
        _Pragma("unroll")                                                      \
        for (int j = 0; j < 12; j++) {                                         \
            int idx = ((h) * 12 + j) * 128 + ptid;                             \
            int o   = idx & 7;                                                 \
            int row = idx >> 3;                                                \
            int ch  = row >> 7;                                                \
            int br  = row & 127;                                               \
            const float* g = u + ((size_t)((bbase + br) * 3 + ch)) * TTOT      \
                               + (t0v) + 4 * o;                                \
            pf[j] = *reinterpret_cast<const float4*>(g);                       \
        }                                                                      \
    }
#define ST_BATCH(dst, h, pf)                                                   \
    {                                                                          \
        _Pragma("unroll")                                                      \
        for (int j = 0; j < 12; j++) {                                         \
            int idx = ((h) * 12 + j) * 128 + ptid;                             \
            int o   = idx & 7;                                                 \
            int row = idx >> 3;                                                \
            int ch  = row >> 7;                                                \
            int br  = row & 127;                                               \
            float* p = (dst) + ch * CHSZ + (4 * o) * BPAD + br;                \
            p[0 * BPAD] = pf[j].x;                                             \
            p[1 * BPAD] = pf[j].y;                                             \
            p[2 * BPAD] = pf[j].z;                                             \
            p[3 * BPAD] = pf[j].w;                                             \
        }                                                                      \
    }
#define DRAIN_SBUF(src, t0v)                                                   \
    {                                                                          \
        _Pragma("unroll")                                                      \
        for (int q = 0; q < 24; q++) {                                         \
            int idx = q * 128 + ptid;                                          \
            int o   = idx & 7;                                                 \
            int row = idx >> 3;                                                \
            int ch  = row >> 7;                                                \
            int br  = row & 127;                                               \
            const float* p = (src) + ch * CHSZ + (4 * o) * BPAD + br;          \
            float4 v = make_float4(p[0], p[BPAD], p[2 * BPAD], p[3 * BPAD]);   \
            float* g = s + ((size_t)((bbase + br) * 3 + ch)) * TTOT            \
                         + (t0v) + 4 * o;                                      \
            *reinterpret_cast<float4*>(g) = v;                                 \
        }                                                                      \
    }

    // prime tile 0
    if (is_prod) {
        float4 pa[12], pb[12];
        LD_BATCH(start, 0, pa);
        LD_BATCH(start, 1, pb);
        ST_BATCH(ubuf[0], 0, pa);
        ST_BATCH(ubuf[0], 1, pb);
    }
    __syncthreads();

    float y0 = 0.f, y1 = 0.f, y2 = 0.f;

    for (int i = 0; i < ntiles; i++) {
        const int t0 = start + i * TTILE;

        if (!is_prod) {
            // ------------- consumer: pure scan of tile i -------------
            const float* Bc = ubuf[i & 1];
            float*       Sb = sbuf[i & 1];
            const bool is_commit = (i >= commit_i0);
#pragma unroll
            for (int t = 0; t < TTILE; t++) {
                const float u0 = Bc[0 * CHSZ + t * BPAD + ptid];
                const float u1 = Bc[1 * CHSZ + t * BPAD + ptid];
                const float u2 = Bc[2 * CHSZ + t * BPAD + ptid];
                const float w0v = fmaf(ALPHA_F, y0, u0);
                const float w1v = fmaf(ALPHA_F, y1, u1);
                const float w2v = fmaf(ALPHA_F, y2, u2);
                const bool g01 = (w0v >= w1v), g02 = (w0v >= w2v), g12 = (w1v >= w2v);
                const bool f0 = g01 & g02 & (w0v >= 1.0f);
                const bool f1 = (!g01) & g12 & (w1v >= 1.0f);
                const bool f2 = (!g02) & (!g12) & (w2v >= 1.0f);
                const float a  = f0 ? 1.0f : 0.0f;
                const float bb = f1 ? 1.0f : 0.0f;
                const float cc = f2 ? 1.0f : 0.0f;
                y0 = w0v - a; y1 = w1v - bb; y2 = w2v - cc;
                if (is_commit) {
                    Sb[0 * CHSZ + t * BPAD + ptid] = a;
                    Sb[1 * CHSZ + t * BPAD + ptid] = bb;
                    Sb[2 * CHSZ + t * BPAD + ptid] = cc;
                }
            }
        } else {
            // ------------- producer: stage tile i+1, drain spikes of tile i-1
            if (i + 1 < ntiles) {
                float4 pa[12], pb[12];
                LD_BATCH(t0 + TTILE, 0, pa);
                LD_BATCH(t0 + TTILE, 1, pb);
                if (i >= commit_i0 + 1)
                    DRAIN_SBUF(sbuf[(i - 1) & 1], t0 - TTILE);   // overlaps LDG latency
                ST_BATCH(ubuf[(i + 1) & 1], 0, pa);
                ST_BATCH(ubuf[(i + 1) & 1], 1, pb);
            } else {
                if (i >= commit_i0 + 1)
                    DRAIN_SBUF(sbuf[(i - 1) & 1], t0 - TTILE);
            }
        }

        __syncthreads();   // tile i consumed + spikes written; tile i+1 staged;
                           // sbuf[(i-1)&1] drained before consumers reuse it at i+1
    }

    // epilogue: drain last commit tile's spikes
    if (is_prod) {
        const int ilast = ntiles - 1;
        DRAIN_SBUF(sbuf[ilast & 1], start + ilast * TTILE);
    }
#undef LD_BATCH
#undef ST_BATCH
#undef DRAIN_SBUF
}

// ---------------------------------------------------------------------------
// Launch. Inputs: x [256*16384], w0 [8], w1 [16], w2 [32], y (unused).
// Output: concat(u, s_all), both [256, 3, 16384] float32.
// ---------------------------------------------------------------------------
extern "C" void kernel_launch(void* const* d_in, const int* in_sizes, int n_in,
                              void* d_out, int out_size)
{
    const float* x  = (const float*)d_in[0];
    const float* w0 = (const float*)d_in[1];
    const float* w1 = (const float*)d_in[2];
    const float* w2 = (const float*)d_in[3];

    float* u = (float*)d_out;
    float* s = u + (size_t)BB * 3 * TTOT;

    cudaFuncSetAttribute(lif_kernel, cudaFuncAttributeMaxDynamicSharedMemorySize,
                         LIF_SMEM_BYTES);

    dim3 cgrid(BB, TTOT / 2048);
    conv_kernel<<<cgrid, 512>>>(x, w0, w1, w2, u);

    lif_kernel<<<NCHUNK * 2, 256, LIF_SMEM_BYTES>>>(u, s);
}

// round 7
// speedup vs baseline: 1.3566x; 1.0377x over previous
#include <cuda_runtime.h>

// Problem constants
#define BB   256
#define TTOT 16384
#define ALPHA_F 0.95f

// LIF chunking (R3-verified exact): 64 chunks of 256, warm-up 512
#define LCHUNK 256
#define WARM   512
#define NCHUNK (TTOT / LCHUNK)   // 64

// lif smem tiling: tile = [3ch][32 t][128 b pad 129]
#define TTILE 32
#define BPAD  129
#define CHSZ  (TTILE * BPAD)            // 4128 floats
#define UBUF  (3 * CHSZ)                // 12384 floats = 49536 B
#define LIF_SMEM_BYTES (4 * UBUF * 4)   // 2 u-buffers + 2 s-buffers = 198144 B

// ---------------------------------------------------------------------------
// Kernel 1: causal conv (R3 version, measured ~21.6us).
// ---------------------------------------------------------------------------
__global__ __launch_bounds__(512) void conv_kernel(
    const float* __restrict__ x,
    const float* __restrict__ w0,
    const float* __restrict__ w1,
    const float* __restrict__ w2,
    float* __restrict__ u)
{
    __shared__ float xs[2080];      // 31 halo + 2048 tile (+1 pad)

    const int b    = blockIdx.x;    // 0..255
    const int tile = blockIdx.y;    // 0..7
    const int t0   = tile * 2048;
    const float* xb = x + (size_t)b * TTOT;

    for (int i = threadIdx.x; i < 2080; i += 512) {
        int gi = t0 + i - 31;
        xs[i] = (gi >= 0 && gi < TTOT) ? xb[gi] : 0.0f;
    }

    float W2[32], W1[16], W0[8];
#pragma unroll
    for (int i = 0; i < 32; i++) W2[i] = w2[i] * 0.1767766952966369f;   // 1/sqrt(32)
#pragma unroll
    for (int i = 0; i < 16; i++) W1[i] = w1[i] * 0.25f;                 // 1/sqrt(16)
#pragma unroll
    for (int i = 0; i < 8;  i++) W0[i] = w0[i] * 0.3535533905932738f;   // 1/sqrt(8)

    __syncthreads();

    const int tt0 = threadIdx.x * 4;

    float xv[36];
#pragma unroll
    for (int q = 0; q < 9; q++) {
        float4 v = *reinterpret_cast<const float4*>(&xs[tt0 + 4 * q]);
        xv[4 * q + 0] = v.x; xv[4 * q + 1] = v.y;
        xv[4 * q + 2] = v.z; xv[4 * q + 3] = v.w;
    }

    float a0[4] = {0.f, 0.f, 0.f, 0.f};
    float a1[4] = {0.f, 0.f, 0.f, 0.f};
    float a2[4] = {0.f, 0.f, 0.f, 0.f};

#pragma unroll
    for (int kk = 0; kk < 32; kk++)
#pragma unroll
        for (int r = 0; r < 4; r++)
            a2[r] = fmaf(W2[kk], xv[kk + r], a2[r]);
#pragma unroll
    for (int kk = 0; kk < 16; kk++)
#pragma unroll
        for (int r = 0; r < 4; r++)
            a1[r] = fmaf(W1[kk], xv[16 + kk + r], a1[r]);
#pragma unroll
    for (int kk = 0; kk < 8; kk++)
#pragma unroll
        for (int r = 0; r < 4; r++)
            a0[r] = fmaf(W0[kk], xv[24 + kk + r], a0[r]);

    const int t = t0 + tt0;
    float* ub = u + (size_t)b * 3 * TTOT;
    *reinterpret_cast<float4*>(ub + 0 * TTOT + t) = make_float4(a0[0], a0[1], a0[2], a0[3]);
    *reinterpret_cast<float4*>(ub + 1 * TTOT + t) = make_float4(a1[0], a1[1], a1[2], a1[3]);
    *reinterpret_cast<float4*>(ub + 2 * TTOT + t) = make_float4(a2[0], a2[1], a2[2], a2[3]);
}

// ---------------------------------------------------------------------------
// Kernel 2: LIF + WTA scan, warp-specialized.
// Block = 256 thr: warps 0-3 consumers (scan, 1 batch each of 128),
// warps 4-7 producers (stage next u tile, drain spike tiles).
// Grid = 128 = (chunk 0..63) x (batch half). One __syncthreads per tile.
// ---------------------------------------------------------------------------
__global__ __launch_bounds__(256) void lif_kernel(
    const float* __restrict__ u,
    float* __restrict__ s)
{
    extern __shared__ float sm[];
    float* ubuf[2] = { sm, sm + UBUF };
    float* sbuf[2] = { sm + 2 * UBUF, sm + 3 * UBUF };

    const int tid   = threadIdx.x;
    const int c     = (int)blockIdx.x >> 1;
    const int bbase = ((int)blockIdx.x & 1) << 7;

    const int commit = c * LCHUNK;
    int start = commit - WARM; if (start < 0) start = 0;
    const int ntiles    = (commit + LCHUNK - start) >> 5;
    const int commit_i0 = (commit - start) >> 5;   // first commit tile index

    const bool is_prod = (tid >= 128);
    const int  ptid    = tid & 127;                // role-local id

    // producer staging map: 3072 16B-chunks per tile, 24 per producer thread.
    // idx = (h*12 + j)*128 + ptid ; o = idx&7 ; row = idx>>3 (= ch*128 + br)
#define LD_BATCH(t0v, h, pf)                                                   \
    {                                                                          \
        _Pragma("unroll")                                                      \
        for (int j = 0; j < 12; j++) {                                         \
            int idx = ((h) * 12 + j) * 128 + ptid;                             \
            int o   = idx & 7;                                                 \
            int row = idx >> 3;                                                \
            int ch  = row >> 7;                                                \
            int br  = row & 127;                                               \
            const float* g = u + ((size_t)((bbase + br) * 3 + ch)) * TTOT      \
                               + (t0v) + 4 * o;                                \
            pf[j] = *reinterpret_cast<const float4*>(g);                       \
        }                                                                      \
    }
#define ST_BATCH(dst, h, pf)                                                   \
    {                                                                          \
        _Pragma("unroll")                                                      \
        for (int j = 0; j < 12; j++) {                                         \
            int idx = ((h) * 12 + j) * 128 + ptid;                             \
            int o   = idx & 7;                                                 \
            int row = idx >> 3;                                                \
            int ch  = row >> 7;                                                \
            int br  = row & 127;                                               \
            float* p = (dst) + ch * CHSZ + (4 * o) * BPAD + br;                \
            p[0 * BPAD] = pf[j].x;                                             \
            p[1 * BPAD] = pf[j].y;                                             \
            p[2 * BPAD] = pf[j].z;                                             \
            p[3 * BPAD] = pf[j].w;                                             \
        }                                                                      \
    }
#define DRAIN_SBUF(src, t0v)                                                   \
    {                                                                          \
        _Pragma("unroll")                                                      \
        for (int q = 0; q < 24; q++) {                                         \
            int idx = q * 128 + ptid;                                          \
            int o   = idx & 7;                                                 \
            int row = idx >> 3;                                                \
            int ch  = row >> 7;                                                \
            int br  = row & 127;                                               \
            const float* p = (src) + ch * CHSZ + (4 * o) * BPAD + br;          \
            float4 v = make_float4(p[0], p[BPAD], p[2 * BPAD], p[3 * BPAD]);   \
            float* g = s + ((size_t)((bbase + br) * 3 + ch)) * TTOT            \
                         + (t0v) + 4 * o;                                      \
            *reinterpret_cast<float4*>(g) = v;                                 \
        }                                                                      \
    }

    // prime tile 0
    if (is_prod) {
        float4 pa[12], pb[12];
        LD_BATCH(start, 0, pa);
        LD_BATCH(start, 1, pb);
        ST_BATCH(ubuf[0], 0, pa);
        ST_BATCH(ubuf[0], 1, pb);
    }
    __syncthreads();

    float y0 = 0.f, y1 = 0.f, y2 = 0.f;

    for (int i = 0; i < ntiles; i++) {
        const int t0 = start + i * TTILE;

        if (!is_prod) {
            // ------------- consumer: pure scan of tile i -------------
            const float* Bc = ubuf[i & 1];
            float*       Sb = sbuf[i & 1];
            const bool is_commit = (i >= commit_i0);
#pragma unroll
            for (int t = 0; t < TTILE; t++) {
                const float u0 = Bc[0 * CHSZ + t * BPAD + ptid];
                const float u1 = Bc[1 * CHSZ + t * BPAD + ptid];
                const float u2 = Bc[2 * CHSZ + t * BPAD + ptid];
                const float w0v = fmaf(ALPHA_F, y0, u0);
                const float w1v = fmaf(ALPHA_F, y1, u1);
                const float w2v = fmaf(ALPHA_F, y2, u2);
                const bool g01 = (w0v >= w1v), g02 = (w0v >= w2v), g12 = (w1v >= w2v);
                const bool f0 = g01 & g02 & (w0v >= 1.0f);
                const bool f1 = (!g01) & g12 & (w1v >= 1.0f);
                const bool f2 = (!g02) & (!g12) & (w2v >= 1.0f);
                const float a  = f0 ? 1.0f : 0.0f;
                const float bb = f1 ? 1.0f : 0.0f;
                const float cc = f2 ? 1.0f : 0.0f;
                y0 = w0v - a; y1 = w1v - bb; y2 = w2v - cc;
                if (is_commit) {
                    Sb[0 * CHSZ + t * BPAD + ptid] = a;
                    Sb[1 * CHSZ + t * BPAD + ptid] = bb;
                    Sb[2 * CHSZ + t * BPAD + ptid] = cc;
                }
            }
        } else {
            // ------------- producer: stage tile i+1, drain spikes of tile i-1
            if (i + 1 < ntiles) {
                float4 pa[12], pb[12];
                LD_BATCH(t0 + TTILE, 0, pa);
                LD_BATCH(t0 + TTILE, 1, pb);
                if (i >= commit_i0 + 1)
                    DRAIN_SBUF(sbuf[(i - 1) & 1], t0 - TTILE);   // overlaps LDG latency
                ST_BATCH(ubuf[(i + 1) & 1], 0, pa);
                ST_BATCH(ubuf[(i + 1) & 1], 1, pb);
            } else {
                if (i >= commit_i0 + 1)
                    DRAIN_SBUF(sbuf[(i - 1) & 1], t0 - TTILE);
            }
        }

        __syncthreads();   // tile i consumed + spikes written; tile i+1 staged;
                           // sbuf[(i-1)&1] drained before consumers reuse it at i+1
    }

    // epilogue: drain last commit tile's spikes
    if (is_prod) {
        const int ilast = ntiles - 1;
        DRAIN_SBUF(sbuf[ilast & 1], start + ilast * TTILE);
    }
#undef LD_BATCH
#undef ST_BATCH
#undef DRAIN_SBUF
}

// ---------------------------------------------------------------------------
// Launch. Inputs: x [256*16384], w0 [8], w1 [16], w2 [32], y (unused).
// Output: concat(u, s_all), both [256, 3, 16384] float32.
// ---------------------------------------------------------------------------
extern "C" void kernel_launch(void* const* d_in, const int* in_sizes, int n_in,
                              void* d_out, int out_size)
{
    const float* x  = (const float*)d_in[0];
    const float* w0 = (const float*)d_in[1];
    const float* w1 = (const float*)d_in[2];
    const float* w2 = (const float*)d_in[3];

    float* u = (float*)d_out;
    float* s = u + (size_t)BB * 3 * TTOT;

    cudaFuncSetAttribute(lif_kernel, cudaFuncAttributeMaxDynamicSharedMemorySize,
                         LIF_SMEM_BYTES);

    dim3 cgrid(BB, TTOT / 2048);
    conv_kernel<<<cgrid, 512>>>(x, w0, w1, w2, u);

    lif_kernel<<<NCHUNK * 2, 256, LIF_SMEM_BYTES>>>(u, s);
}

// round 9
// speedup vs baseline: 1.6060x; 1.1838x over previous
#include <cuda_runtime.h>

// Problem constants
#define BB   256
#define TTOT 16384
#define ALPHA_F 0.95f

// LIF chunking (verified exact): 64 chunks of 256, warm-up 512
#define LCHUNK 256
#define WARM   512
#define NCHUNK (TTOT / LCHUNK)   // 64

// lif smem tiling: u tile = [3ch][32 t][128 b pad 129]
#define TTILE 32
#define BPAD  129
#define CHSZ  (TTILE * BPAD)            // 4128 floats
#define UBUF  (3 * CHSZ)                // 12384 floats = 49536 B
#define MROWS 384                       // 3ch * 128b mask words per tile
#define LIF_SMEM_BYTES (2 * UBUF * 4 + 2 * MROWS * 4)   // 102144 B

// ---------------------------------------------------------------------------
// Kernel 1: causal conv (measured ~21.6us).
// ---------------------------------------------------------------------------
__global__ __launch_bounds__(512) void conv_kernel(
    const float* __restrict__ x,
    const float* __restrict__ w0,
    const float* __restrict__ w1,
    const float* __restrict__ w2,
    float* __restrict__ u)
{
    __shared__ float xs[2080];

    const int b    = blockIdx.x;
    const int tile = blockIdx.y;
    const int t0   = tile * 2048;
    const float* xb = x + (size_t)b * TTOT;

    for (int i = threadIdx.x; i < 2080; i += 512) {
        int gi = t0 + i - 31;
        xs[i] = (gi >= 0 && gi < TTOT) ? xb[gi] : 0.0f;
    }

    float W2[32], W1[16], W0[8];
#pragma unroll
    for (int i = 0; i < 32; i++) W2[i] = w2[i] * 0.1767766952966369f;
#pragma unroll
    for (int i = 0; i < 16; i++) W1[i] = w1[i] * 0.25f;
#pragma unroll
    for (int i = 0; i < 8;  i++) W0[i] = w0[i] * 0.3535533905932738f;

    __syncthreads();

    const int tt0 = threadIdx.x * 4;

    float xv[36];
#pragma unroll
    for (int q = 0; q < 9; q++) {
        float4 v = *reinterpret_cast<const float4*>(&xs[tt0 + 4 * q]);
        xv[4 * q + 0] = v.x; xv[4 * q + 1] = v.y;
        xv[4 * q + 2] = v.z; xv[4 * q + 3] = v.w;
    }

    float a0[4] = {0.f, 0.f, 0.f, 0.f};
    float a1[4] = {0.f, 0.f, 0.f, 0.f};
    float a2[4] = {0.f, 0.f, 0.f, 0.f};

#pragma unroll
    for (int kk = 0; kk < 32; kk++)
#pragma unroll
        for (int r = 0; r < 4; r++)
            a2[r] = fmaf(W2[kk], xv[kk + r], a2[r]);
#pragma unroll
    for (int kk = 0; kk < 16; kk++)
#pragma unroll
        for (int r = 0; r < 4; r++)
            a1[r] = fmaf(W1[kk], xv[16 + kk + r], a1[r]);
#pragma unroll
    for (int kk = 0; kk < 8; kk++)
#pragma unroll
        for (int r = 0; r < 4; r++)
            a0[r] = fmaf(W0[kk], xv[24 + kk + r], a0[r]);

    const int t = t0 + tt0;
    float* ub = u + (size_t)b * 3 * TTOT;
    *reinterpret_cast<float4*>(ub + 0 * TTOT + t) = make_float4(a0[0], a0[1], a0[2], a0[3]);
    *reinterpret_cast<float4*>(ub + 1 * TTOT + t) = make_float4(a1[0], a1[1], a1[2], a1[3]);
    *reinterpret_cast<float4*>(ub + 2 * TTOT + t) = make_float4(a2[0], a2[1], a2[2], a2[3]);
}

// ---------------------------------------------------------------------------
// Kernel 2: LIF + WTA scan, warp-specialized, bitmask spikes.
// Block = 256 thr: warps 0-3 consumers (pure scan, masks in registers),
// warps 4-7 producers (stage next u tile, expand+drain mask tiles).
// Grid = 128 = (chunk 0..63) x (batch half).
// ---------------------------------------------------------------------------
__global__ __launch_bounds__(256) void lif_kernel(
    const float* __restrict__ u,
    float* __restrict__ s)
{
    extern __shared__ float sm[];
    float*    ubuf[2] = { sm, sm + UBUF };
    unsigned* mbuf[2] = { reinterpret_cast<unsigned*>(sm + 2 * UBUF),
                          reinterpret_cast<unsigned*>(sm + 2 * UBUF) + MROWS };

    const int tid   = threadIdx.x;
    const int c     = (int)blockIdx.x >> 1;
    const int bbase = ((int)blockIdx.x & 1) << 7;

    const int commit = c * LCHUNK;
    int start = commit - WARM; if (start < 0) start = 0;
    const int ntiles    = (commit + LCHUNK - start) >> 5;
    const int commit_i0 = (commit - start) >> 5;

    const bool is_prod = (tid >= 128);
    const int  ptid    = tid & 127;

#define LD_BATCH(t0v, h, pf)                                                   \
    {                                                                          \
        _Pragma("unroll")                                                      \
        for (int j = 0; j < 12; j++) {                                         \
            int idx = ((h) * 12 + j) * 128 + ptid;                             \
            int o   = idx & 7;                                                 \
            int row = idx >> 3;                                                \
            int ch  = row >> 7;                                                \
            int br  = row & 127;                                               \
            const float* g = u + ((size_t)((bbase + br) * 3 + ch)) * TTOT      \
                               + (t0v) + 4 * o;                                \
            pf[j] = *reinterpret_cast<const float4*>(g);                       \
        }                                                                      \
    }
#define ST_BATCH(dst, h, pf)                                                   \
    {                                                                          \
        _Pragma("unroll")                                                      \
        for (int j = 0; j < 12; j++) {                                         \
            int idx = ((h) * 12 + j) * 128 + ptid;                             \
            int o   = idx & 7;                                                 \
            int row = idx >> 3;                                                \
            int ch  = row >> 7;                                                \
            int br  = row & 127;                                               \
            float* p = (dst) + ch * CHSZ + (4 * o) * BPAD + br;                \
            p[0 * BPAD] = pf[j].x;                                             \
            p[1 * BPAD] = pf[j].y;                                             \
            p[2 * BPAD] = pf[j].z;                                             \
            p[3 * BPAD] = pf[j].w;                                             \
        }                                                                      \
    }
    // mask drain: tile spikes = 384 rows x 32 t = 3072 float4, 24 per thread.
    // idx = q*128+ptid in [0,3072) ; o = idx&7 (float4 within row) ; row = idx>>3
#define DRAIN_MASKS(mb, t0v)                                                   \
    {                                                                          \
        _Pragma("unroll")                                                      \
        for (int q = 0; q < 24; q++) {                                         \
            int idx = q * 128 + ptid;                                          \
            int o   = idx & 7;                                                 \
            int row = idx >> 3;                                                \
            int ch  = row >> 7;                                                \
            int br  = row & 127;                                               \
            unsigned m = (mb)[row];                                            \
            float4 v;                                                          \
            v.x = (m >> (4 * o + 0)) & 1u ? 1.0f : 0.0f;                       \
            v.y = (m >> (4 * o + 1)) & 1u ? 1.0f : 0.0f;                       \
            v.z = (m >> (4 * o + 2)) & 1u ? 1.0f : 0.0f;                       \
            v.w = (m >> (4 * o + 3)) & 1u ? 1.0f : 0.0f;                       \
            float* g = s + ((size_t)((bbase + br) * 3 + ch)) * TTOT            \
                         + (t0v) + 4 * o;                                      \
            *reinterpret_cast<float4*>(g) = v;                                 \
        }                                                                      \
    }

    // prime tile 0
    if (is_prod) {
        float4 pa[12], pb[12];
        LD_BATCH(start, 0, pa);
        LD_BATCH(start, 1, pb);
        ST_BATCH(ubuf[0], 0, pa);
        ST_BATCH(ubuf[0], 1, pb);
    }
    __syncthreads();

    float y0 = 0.f, y1 = 0.f, y2 = 0.f;

    for (int i = 0; i < ntiles; i++) {
        const int t0 = start + i * TTILE;

        if (!is_prod) {
            // -------- consumer: pure scan of tile i (no smem stores in loop)
            const float* Pc = ubuf[i & 1] + ptid;
            if (i >= commit_i0) {
                unsigned m0 = 0u, m1 = 0u, m2 = 0u;
#pragma unroll
                for (int t = 0; t < TTILE; t++) {
                    const float u0 = Pc[0 * CHSZ + t * BPAD];
                    const float u1 = Pc[1 * CHSZ + t * BPAD];
                    const float u2 = Pc[2 * CHSZ + t * BPAD];
                    const float w0v = fmaf(ALPHA_F, y0, u0);
                    const float w1v = fmaf(ALPHA_F, y1, u1);
                    const float w2v = fmaf(ALPHA_F, y2, u2);
                    const bool g01 = (w0v >= w1v), g02 = (w0v >= w2v), g12 = (w1v >= w2v);
                    const bool f0 = g01 & g02 & (w0v >= 1.0f);
                    const bool f1 = (!g01) & g12 & (w1v >= 1.0f);
                    const bool f2 = (!g02) & (!g12) & (w2v >= 1.0f);
                    y0 = w0v - (f0 ? 1.0f : 0.0f);
                    y1 = w1v - (f1 ? 1.0f : 0.0f);
                    y2 = w2v - (f2 ? 1.0f : 0.0f);
                    m0 |= f0 ? (1u << t) : 0u;
                    m1 |= f1 ? (1u << t) : 0u;
                    m2 |= f2 ? (1u << t) : 0u;
                }
                unsigned* mb = mbuf[i & 1];
                mb[0 * 128 + ptid] = m0;
                mb[1 * 128 + ptid] = m1;
                mb[2 * 128 + ptid] = m2;
            } else {
#pragma unroll
                for (int t = 0; t < TTILE; t++) {
                    const float u0 = Pc[0 * CHSZ + t * BPAD];
                    const float u1 = Pc[1 * CHSZ + t * BPAD];
                    const float u2 = Pc[2 * CHSZ + t * BPAD];
                    const float w0v = fmaf(ALPHA_F, y0, u0);
                    const float w1v = fmaf(ALPHA_F, y1, u1);
                    const float w2v = fmaf(ALPHA_F, y2, u2);
                    const bool g01 = (w0v >= w1v), g02 = (w0v >= w2v), g12 = (w1v >= w2v);
                    const bool f0 = g01 & g02 & (w0v >= 1.0f);
                    const bool f1 = (!g01) & g12 & (w1v >= 1.0f);
                    const bool f2 = (!g02) & (!g12) & (w2v >= 1.0f);
                    y0 = w0v - (f0 ? 1.0f : 0.0f);
                    y1 = w1v - (f1 ? 1.0f : 0.0f);
                    y2 = w2v - (f2 ? 1.0f : 0.0f);
                }
            }
        } else {
            // -------- producer: stage tile i+1, drain masks of tile i-1
            if (i + 1 < ntiles) {
                float4 pa[12], pb[12];
                LD_BATCH(t0 + TTILE, 0, pa);
                LD_BATCH(t0 + TTILE, 1, pb);
                if (i >= commit_i0 + 1)
                    DRAIN_MASKS(mbuf[(i - 1) & 1], t0 - TTILE);   // overlaps LDG latency
                ST_BATCH(ubuf[(i + 1) & 1], 0, pa);
                ST_BATCH(ubuf[(i + 1) & 1], 1, pb);
            } else {
                if (i >= commit_i0 + 1)
                    DRAIN_MASKS(mbuf[(i - 1) & 1], t0 - TTILE);
            }
        }

        __syncthreads();
    }

    // epilogue: drain last commit tile's masks
    if (is_prod) {
        const int ilast = ntiles - 1;
        DRAIN_MASKS(mbuf[ilast & 1], start + ilast * TTILE);
    }
#undef LD_BATCH
#undef ST_BATCH
#undef DRAIN_MASKS
}

// ---------------------------------------------------------------------------
// Launch.
// ---------------------------------------------------------------------------
extern "C" void kernel_launch(void* const* d_in, const int* in_sizes, int n_in,
                              void* d_out, int out_size)
{
    const float* x  = (const float*)d_in[0];
    const float* w0 = (const float*)d_in[1];
    const float* w1 = (const float*)d_in[2];
    const float* w2 = (const float*)d_in[3];

    float* u = (float*)d_out;
    float* s = u + (size_t)BB * 3 * TTOT;

    cudaFuncSetAttribute(lif_kernel, cudaFuncAttributeMaxDynamicSharedMemorySize,
                         LIF_SMEM_BYTES);

    dim3 cgrid(BB, TTOT / 2048);
    conv_kernel<<<cgrid, 512>>>(x, w0, w1, w2, u);

    lif_kernel<<<NCHUNK * 2, 256, LIF_SMEM_BYTES>>>(u, s);
}